// round 3
// baseline (speedup 1.0000x reference)
#include <cuda_runtime.h>

#define EPSF 1e-7f
#define ACLIPF (1.0f - 1e-6f)
#define PI_F 3.14159274101257324f

// Scratch for deterministic single-launch reduction (no device allocs allowed).
static __device__ float g_partials[8192];
static __device__ unsigned int g_ticket = 0;   // self-resetting via atomicInc wrap

__device__ __forceinline__ float frcp_approx(float x) {
    float r; asm("rcp.approx.f32 %0, %1;" : "=f"(r) : "f"(x)); return r;
}

// fast sqrt for strictly-positive args (all call sites guarded >= EPSF or >= 1e-6)
__device__ __forceinline__ float fsqrt_pos(float x) {
    return x * rsqrtf(x);
}

// acos approximation for x in [0,1): abs err <= ~6.8e-5
__device__ __forceinline__ float facos_pos(float x) {
    float p = fmaf(x, -0.0187293f, 0.0742610f);
    p = fmaf(x, p, -0.2121144f);
    p = fmaf(x, p, 1.5707288f);
    return fsqrt_pos(1.0f - x) * p;   // 1-x >= 1e-6 after clipping
}

// acos for x in (-1,1) (clipped to +/-ACLIPF)
__device__ __forceinline__ float facos(float x) {
    float v = facos_pos(fabsf(x));
    return (x >= 0.0f) ? v : (PI_F - v);
}

__device__ __forceinline__ float giou_loss(float cx0, float cy0, float r0,
                                           float cx1, float cy1, float r1) {
    float dx = cx0 - cx1, dy = cy0 - cy1;
    float d2 = fmaf(dx, dx, dy * dy);
    float d2c = fmaxf(d2, EPSF);
    float inv_d = rsqrtf(d2c);

    float rsum  = r0 + r1;
    float r0s = r0 * r0, r1s = r1 * r1;
    float rmax2 = fmaxf(r0s, r1s), rmin2 = fminf(r0s, r1s);
    float rdiff = fabsf(r0 - r1);
    float rdiff2 = rdiff * rdiff;
    float rsum2  = rsum * rsum;

    bool lens      = (d2c < rsum2) && (d2c > rdiff2);
    bool contained = d2c <= rdiff2;

    // cos0 = (d2+r0s-r1s)/(2 d r0), cos1 = (d2+r1s-r0s)/(2 d r1)
    // shared reciprocal: 1/r0 = r1*rcp(r0*r1), 1/r1 = r0*rcp(r0*r1)
    float inv_rr = frcp_approx(fmaxf(r0 * r1, 1e-20f));
    float half_invd = 0.5f * inv_d;
    float e = r0s - r1s;
    float cos0 = (d2 + e) * half_invd * (r1 * inv_rr);
    float cos1 = (d2 - e) * half_invd * (r0 * inv_rr);
    cos0 = fminf(fmaxf(cos0, -ACLIPF), ACLIPF);
    cos1 = fminf(fmaxf(cos1, -ACLIPF), ACLIPF);

    // t = (rsum^2 - d^2)(d^2 - rdiff^2); only consumed when lens, so guard unconditionally
    float t = (rsum2 - d2c) * (d2c - rdiff2);
    float lens_area = fmaf(r0s, facos(cos0),
                      fmaf(r1s, facos(cos1),
                           -0.5f * fsqrt_pos(fmaxf(t, EPSF))));

    float inter = lens ? lens_area : (contained ? PI_F * rmin2 : 0.0f);
    float uni = fmaf(PI_F, r0s + r1s, -inter);

    float alpha = facos_pos(fminf(rdiff * inv_d, ACLIPF));   // arg >= 0 always
    float h2 = d2 - rdiff2;                                   // only consumed when !contained
    float hull_open = rmax2 * (PI_F - alpha) + rmin2 * alpha
                      + (rmax2 + 2.0f * fsqrt_pos(rmax2 * rmin2) + rmin2 > 0.0f ? 0.0f : 0.0f)  /* keep simple below */
                      ;
    hull_open += (fmaxf(r0, r1) + fminf(r0, r1)) * fsqrt_pos(fmaxf(h2, EPSF));
    float hull = contained ? PI_F * rmax2 : hull_open;

    // loss = 1 - (inter/U - (hull-uni)/H) with U=max(uni,EPS), H=max(hull,EPS)
    float U = fmaxf(uni, EPSF), H = fmaxf(hull, EPSF);
    float num = inter * H - (hull - uni) * U;
    return 1.0f - __fdividef(num, U * H);
}

// 4 elements per thread via 3 float4 loads per input (coalesced 128-bit over [N,3]).
// Last block (ticket pattern) folds g_partials -> out[0] in a fixed order.
__global__ void __launch_bounds__(256) giou_fused_kernel(
    const float* __restrict__ x, const float* __restrict__ y,
    float* __restrict__ out, int n) {
    int quad = blockIdx.x * blockDim.x + threadIdx.x;
    int base = quad * 4;
    float acc = 0.0f;

    if (base + 3 < n) {
        const float4* x4 = (const float4*)x;
        const float4* y4 = (const float4*)y;
        float4 xa = x4[quad * 3 + 0];
        float4 xb = x4[quad * 3 + 1];
        float4 xc = x4[quad * 3 + 2];
        float4 ya = y4[quad * 3 + 0];
        float4 yb = y4[quad * 3 + 1];
        float4 yc = y4[quad * 3 + 2];
        acc += giou_loss(xa.x, xa.y, xa.z, ya.x, ya.y, ya.z);
        acc += giou_loss(xa.w, xb.x, xb.y, ya.w, yb.x, yb.y);
        acc += giou_loss(xb.z, xb.w, xc.x, yb.z, yb.w, yc.x);
        acc += giou_loss(xc.y, xc.z, xc.w, yc.y, yc.z, yc.w);
    } else if (base < n) {
        for (int i = base; i < n; i++) {
            acc += giou_loss(x[3*i], x[3*i+1], x[3*i+2], y[3*i], y[3*i+1], y[3*i+2]);
        }
    }

    // block reduce
    #pragma unroll
    for (int off = 16; off > 0; off >>= 1)
        acc += __shfl_xor_sync(0xFFFFFFFFu, acc, off);

    __shared__ float warp_sums[8];
    __shared__ bool amLast;
    int lane = threadIdx.x & 31;
    int wid  = threadIdx.x >> 5;
    if (lane == 0) warp_sums[wid] = acc;
    __syncthreads();
    if (wid == 0) {
        float v = (lane < 8) ? warp_sums[lane] : 0.0f;
        #pragma unroll
        for (int off = 4; off > 0; off >>= 1)
            v += __shfl_xor_sync(0xFFFFFFFFu, v, off);
        if (lane == 0) {
            g_partials[blockIdx.x] = v;
            __threadfence();
            unsigned int t = atomicInc(&g_ticket, gridDim.x - 1); // wraps to 0 on last
            amLast = (t == gridDim.x - 1);
        }
    }
    __syncthreads();

    if (amLast) {
        __threadfence();
        int nblocks = gridDim.x;
        float a2 = 0.0f;
        for (int i = threadIdx.x; i < nblocks; i += 256)
            a2 += g_partials[i];                      // fixed order -> deterministic
        #pragma unroll
        for (int off = 16; off > 0; off >>= 1)
            a2 += __shfl_xor_sync(0xFFFFFFFFu, a2, off);
        __syncthreads();                              // reuse warp_sums safely
        if (lane == 0) warp_sums[wid] = a2;
        __syncthreads();
        if (wid == 0) {
            float v = (lane < 8) ? warp_sums[lane] : 0.0f;
            #pragma unroll
            for (int off = 4; off > 0; off >>= 1)
                v += __shfl_xor_sync(0xFFFFFFFFu, v, off);
            if (lane == 0) out[0] = v;
        }
    }
}

extern "C" void kernel_launch(void* const* d_in, const int* in_sizes, int n_in,
                              void* d_out, int out_size) {
    const float* x = (const float*)d_in[0];
    const float* y = (const float*)d_in[1];
    int n = in_sizes[0] / 3;                 // number of circle pairs
    int quads = (n + 3) / 4;                 // 4 elements per thread
    int threads = 256;
    int blocks = (quads + threads - 1) / threads;  // 4096 for N=4194304
    if (blocks > 8192) blocks = 8192;        // g_partials capacity (N fits anyway)

    giou_fused_kernel<<<blocks, threads>>>(x, y, (float*)d_out, n);
}

// round 5
// speedup vs baseline: 1.0660x; 1.0660x over previous
#include <cuda_runtime.h>

#define EPSF 1e-7f
#define ACLIPF (1.0f - 1e-6f)
#define PI_F 3.14159274101257324f

// Scratch for deterministic single-launch reduction (no device allocs allowed).
static __device__ float g_partials[8192];
static __device__ unsigned int g_ticket = 0;   // self-resetting via atomicInc wrap

// fast sqrt for strictly-positive args (all call sites guarded > 0)
__device__ __forceinline__ float fsqrt_pos(float x) {
    return x * rsqrtf(x);
}

// acos approximation for x in [0,1): abs err <= ~6.8e-5
__device__ __forceinline__ float facos_pos(float x) {
    float p = fmaf(x, -0.0187293f, 0.0742610f);
    p = fmaf(x, p, -0.2121144f);
    p = fmaf(x, p, 1.5707288f);
    return fsqrt_pos(1.0f - x) * p;   // 1-x >= 1e-6 after clipping
}

// acos for x in (-1,1) (clipped to +/-ACLIPF)
__device__ __forceinline__ float facos(float x) {
    float v = facos_pos(fabsf(x));
    return (x >= 0.0f) ? v : (PI_F - v);
}

__device__ __forceinline__ float giou_loss(float cx0, float cy0, float r0,
                                           float cx1, float cy1, float r1) {
    float dx = cx0 - cx1, dy = cy0 - cy1;
    float d2 = fmaf(dx, dx, dy * dy);
    float d2c = fmaxf(d2, EPSF);
    float inv_d = rsqrtf(d2c);

    float r0s = r0 * r0, r1s = r1 * r1;
    float e = r0s - r1s;                 // r0^2 - r1^2
    float ae = fabsf(e);                 // rmax^2 - rmin^2
    float rsum  = r0 + r1;
    float rdiff = fabsf(r0 - r1);
    float rsum2  = rsum * rsum;
    float rdiff2 = rdiff * rdiff;

    bool lens      = (d2c < rsum2) && (d2c > rdiff2);
    bool contained = d2c <= rdiff2;

    // cos0 = (d2+e)/(2 d r0), cos1 = (d2-e)/(2 d r1)
    float half_invd = 0.5f * inv_d;
    float cos0 = __fdividef((d2 + e) * half_invd, r0);
    float cos1 = __fdividef((d2 - e) * half_invd, r1);
    cos0 = fminf(fmaxf(cos0, -ACLIPF), ACLIPF);
    cos1 = fminf(fmaxf(cos1, -ACLIPF), ACLIPF);

    // t = (rsum^2 - d^2)(d^2 - rdiff^2); > 0 iff lens, guarded unconditionally
    float t = (rsum2 - d2c) * (d2c - rdiff2);
    float lens_area = fmaf(r0s, facos(cos0),
                      fmaf(r1s, facos(cos1),
                           -0.5f * fsqrt_pos(fmaxf(t, EPSF))));

    float pi_rmin2 = PI_F * fminf(r0s, r1s);
    float pi_rmax2 = PI_F * fmaxf(r0s, r1s);
    float inter = lens ? lens_area : (contained ? pi_rmin2 : 0.0f);
    float uni = pi_rmax2 + pi_rmin2 - inter;

    float alpha = facos_pos(fminf(rdiff * inv_d, ACLIPF));   // arg >= 0 always
    float sqrt_h2 = fsqrt_pos(fmaxf(d2 - rdiff2, EPSF));
    // hull_open = PI*rmax2 - alpha*(rmax2 - rmin2) + rsum*sqrt(h2)
    float hull_open = fmaf(rsum, sqrt_h2, fmaf(alpha, -ae, pi_rmax2));
    float hull = contained ? pi_rmax2 : hull_open;

    // loss = 1 - (inter/U - (hull-uni)/H) with one divide
    float U = fmaxf(uni, EPSF), H = fmaxf(hull, EPSF);
    float num = fmaf(inter, H, -(hull - uni) * U);
    return 1.0f - __fdividef(num, U * H);
}

// 4 elements per thread via 3 float4 loads per input (coalesced 128-bit over [N,3]).
// Last block (ticket pattern) folds g_partials -> out[0] in a fixed order.
__global__ void __launch_bounds__(256) giou_fused_kernel(
    const float* __restrict__ x, const float* __restrict__ y,
    float* __restrict__ out, int n) {
    int quad = blockIdx.x * blockDim.x + threadIdx.x;
    int base = quad * 4;
    float acc = 0.0f;

    if (base + 3 < n) {
        const float4* x4 = (const float4*)x;
        const float4* y4 = (const float4*)y;
        float4 xa = x4[quad * 3 + 0];
        float4 xb = x4[quad * 3 + 1];
        float4 xc = x4[quad * 3 + 2];
        float4 ya = y4[quad * 3 + 0];
        float4 yb = y4[quad * 3 + 1];
        float4 yc = y4[quad * 3 + 2];
        acc += giou_loss(xa.x, xa.y, xa.z, ya.x, ya.y, ya.z);
        acc += giou_loss(xa.w, xb.x, xb.y, ya.w, yb.x, yb.y);
        acc += giou_loss(xb.z, xb.w, xc.x, yb.z, yb.w, yc.x);
        acc += giou_loss(xc.y, xc.z, xc.w, yc.y, yc.z, yc.w);
    } else if (base < n) {
        for (int i = base; i < n; i++) {
            acc += giou_loss(x[3*i], x[3*i+1], x[3*i+2], y[3*i], y[3*i+1], y[3*i+2]);
        }
    }

    // block reduce
    #pragma unroll
    for (int off = 16; off > 0; off >>= 1)
        acc += __shfl_xor_sync(0xFFFFFFFFu, acc, off);

    __shared__ float warp_sums[8];
    __shared__ bool amLast;
    int lane = threadIdx.x & 31;
    int wid  = threadIdx.x >> 5;
    if (lane == 0) warp_sums[wid] = acc;
    __syncthreads();
    if (wid == 0) {
        float v = (lane < 8) ? warp_sums[lane] : 0.0f;
        #pragma unroll
        for (int off = 4; off > 0; off >>= 1)
            v += __shfl_xor_sync(0xFFFFFFFFu, v, off);
        if (lane == 0) {
            g_partials[blockIdx.x] = v;
            __threadfence();
            unsigned int t = atomicInc(&g_ticket, gridDim.x - 1); // wraps to 0 on last
            amLast = (t == gridDim.x - 1);
        }
    }
    __syncthreads();

    if (amLast) {
        __threadfence();
        int nblocks = gridDim.x;
        float a2 = 0.0f;
        for (int i = threadIdx.x; i < nblocks; i += 256)
            a2 += g_partials[i];                      // fixed order -> deterministic
        #pragma unroll
        for (int off = 16; off > 0; off >>= 1)
            a2 += __shfl_xor_sync(0xFFFFFFFFu, a2, off);
        __syncthreads();                              // reuse warp_sums safely
        if (lane == 0) warp_sums[wid] = a2;
        __syncthreads();
        if (wid == 0) {
            float v = (lane < 8) ? warp_sums[lane] : 0.0f;
            #pragma unroll
            for (int off = 4; off > 0; off >>= 1)
                v += __shfl_xor_sync(0xFFFFFFFFu, v, off);
            if (lane == 0) out[0] = v;
        }
    }
}

extern "C" void kernel_launch(void* const* d_in, const int* in_sizes, int n_in,
                              void* d_out, int out_size) {
    const float* x = (const float*)d_in[0];
    const float* y = (const float*)d_in[1];
    int n = in_sizes[0] / 3;                 // number of circle pairs
    int quads = (n + 3) / 4;                 // 4 elements per thread
    int threads = 256;
    int blocks = (quads + threads - 1) / threads;  // 4096 for N=4194304
    if (blocks > 8192) blocks = 8192;        // g_partials capacity (N fits anyway)

    giou_fused_kernel<<<blocks, threads>>>(x, y, (float*)d_out, n);
}

// round 6
// speedup vs baseline: 1.1117x; 1.0429x over previous
#include <cuda_runtime.h>

#define EPSF 1e-7f
#define ACLIPF (1.0f - 1e-6f)
#define PI_F 3.14159274101257324f

// Scratch for deterministic single-launch reduction (no device allocs allowed).
static __device__ float g_partials[8192];
static __device__ unsigned int g_ticket = 0;   // self-resetting via atomicInc wrap

// fast sqrt for strictly-positive args (all call sites guarded > 0)
__device__ __forceinline__ float fsqrt_pos(float x) {
    return x * rsqrtf(x);
}

// acos approximation for x in [0,1): abs err <= ~6.8e-5
__device__ __forceinline__ float facos_pos(float x) {
    float p = fmaf(x, -0.0187293f, 0.0742610f);
    p = fmaf(x, p, -0.2121144f);
    p = fmaf(x, p, 1.5707288f);
    return fsqrt_pos(1.0f - x) * p;   // 1-x >= 1e-6 after clipping
}

// acos for x in (-1,1) (clipped to +/-ACLIPF)
__device__ __forceinline__ float facos(float x) {
    float v = facos_pos(fabsf(x));
    return (x >= 0.0f) ? v : (PI_F - v);
}

__device__ __forceinline__ float giou_loss(float cx0, float cy0, float r0,
                                           float cx1, float cy1, float r1) {
    float dx = cx0 - cx1, dy = cy0 - cy1;
    float d2 = fmaf(dx, dx, dy * dy);
    float d2c = fmaxf(d2, EPSF);
    float inv_d = rsqrtf(d2c);

    float r0s = r0 * r0, r1s = r1 * r1;
    float e = r0s - r1s;                 // r0^2 - r1^2
    float rsum  = r0 + r1;
    float rdiff = fabsf(r0 - r1);
    float rsum2  = rsum * rsum;
    float rdiff2 = rdiff * rdiff;

    bool lens      = (d2c < rsum2) && (d2c > rdiff2);
    bool contained = d2c <= rdiff2;

    // cos0 = (d2+e)/(2 d r0), cos1 = (d2-e)/(2 d r1); consume each immediately
    float half_invd = 0.5f * inv_d;
    float cos0 = __fdividef((d2 + e) * half_invd, r0);
    cos0 = fminf(fmaxf(cos0, -ACLIPF), ACLIPF);
    float acos0 = facos(cos0);
    float cos1 = __fdividef((d2 - e) * half_invd, r1);
    cos1 = fminf(fmaxf(cos1, -ACLIPF), ACLIPF);
    float acos1 = facos(cos1);

    // t = (rsum^2 - d^2)(d^2 - rdiff^2); > 0 iff lens, guarded unconditionally
    float t = (rsum2 - d2c) * (d2c - rdiff2);
    float lens_area = fmaf(r0s, acos0,
                      fmaf(r1s, acos1,
                           -0.5f * fsqrt_pos(fmaxf(t, EPSF))));

    float pi_rmin2 = PI_F * fminf(r0s, r1s);
    float pi_rmax2 = PI_F * fmaxf(r0s, r1s);
    float inter = lens ? lens_area : (contained ? pi_rmin2 : 0.0f);
    float uni = pi_rmax2 + pi_rmin2 - inter;

    float alpha = facos_pos(fminf(rdiff * inv_d, ACLIPF));   // arg >= 0 always
    float sqrt_h2 = fsqrt_pos(fmaxf(d2 - rdiff2, EPSF));
    // hull_open = PI*rmax2 - alpha*(rmax2 - rmin2) + rsum*sqrt(h2)
    float hull_open = fmaf(rsum, sqrt_h2, fmaf(alpha, -fabsf(e), pi_rmax2));
    float hull = contained ? pi_rmax2 : hull_open;

    // loss = 1 - (inter/U - (hull-uni)/H) with one divide
    float U = fmaxf(uni, EPSF), H = fmaxf(hull, EPSF);
    float num = fmaf(inter, H, -(hull - uni) * U);
    return 1.0f - __fdividef(num, U * H);
}

// 4 elements per thread via 3 float4 loads per input (coalesced 128-bit over [N,3]).
// __launch_bounds__(256, 8): cap at 32 regs -> 2048 threads/SM resident.
// Last block (ticket pattern) folds g_partials -> out[0] in a fixed order.
__global__ void __launch_bounds__(256, 8) giou_fused_kernel(
    const float* __restrict__ x, const float* __restrict__ y,
    float* __restrict__ out, int n) {
    int quad = blockIdx.x * blockDim.x + threadIdx.x;
    int base = quad * 4;
    float acc = 0.0f;

    if (base + 3 < n) {
        const float4* x4 = (const float4*)x;
        const float4* y4 = (const float4*)y;
        float4 xa = x4[quad * 3 + 0];
        float4 ya = y4[quad * 3 + 0];
        float4 xb = x4[quad * 3 + 1];
        float4 yb = y4[quad * 3 + 1];
        float4 xc = x4[quad * 3 + 2];
        float4 yc = y4[quad * 3 + 2];
        acc += giou_loss(xa.x, xa.y, xa.z, ya.x, ya.y, ya.z);
        acc += giou_loss(xa.w, xb.x, xb.y, ya.w, yb.x, yb.y);
        acc += giou_loss(xb.z, xb.w, xc.x, yb.z, yb.w, yc.x);
        acc += giou_loss(xc.y, xc.z, xc.w, yc.y, yc.z, yc.w);
    } else if (base < n) {
        for (int i = base; i < n; i++) {
            acc += giou_loss(x[3*i], x[3*i+1], x[3*i+2], y[3*i], y[3*i+1], y[3*i+2]);
        }
    }

    // block reduce
    #pragma unroll
    for (int off = 16; off > 0; off >>= 1)
        acc += __shfl_xor_sync(0xFFFFFFFFu, acc, off);

    __shared__ float warp_sums[8];
    __shared__ bool amLast;
    int lane = threadIdx.x & 31;
    int wid  = threadIdx.x >> 5;
    if (lane == 0) warp_sums[wid] = acc;
    __syncthreads();
    if (wid == 0) {
        float v = (lane < 8) ? warp_sums[lane] : 0.0f;
        #pragma unroll
        for (int off = 4; off > 0; off >>= 1)
            v += __shfl_xor_sync(0xFFFFFFFFu, v, off);
        if (lane == 0) {
            g_partials[blockIdx.x] = v;
            __threadfence();
            unsigned int t = atomicInc(&g_ticket, gridDim.x - 1); // wraps to 0 on last
            amLast = (t == gridDim.x - 1);
        }
    }
    __syncthreads();

    if (amLast) {
        __threadfence();
        int nblocks = gridDim.x;
        float a2 = 0.0f;
        for (int i = threadIdx.x; i < nblocks; i += 256)
            a2 += g_partials[i];                      // fixed order -> deterministic
        #pragma unroll
        for (int off = 16; off > 0; off >>= 1)
            a2 += __shfl_xor_sync(0xFFFFFFFFu, a2, off);
        __syncthreads();                              // reuse warp_sums safely
        if (lane == 0) warp_sums[wid] = a2;
        __syncthreads();
        if (wid == 0) {
            float v = (lane < 8) ? warp_sums[lane] : 0.0f;
            #pragma unroll
            for (int off = 4; off > 0; off >>= 1)
                v += __shfl_xor_sync(0xFFFFFFFFu, v, off);
            if (lane == 0) out[0] = v;
        }
    }
}

extern "C" void kernel_launch(void* const* d_in, const int* in_sizes, int n_in,
                              void* d_out, int out_size) {
    const float* x = (const float*)d_in[0];
    const float* y = (const float*)d_in[1];
    int n = in_sizes[0] / 3;                 // number of circle pairs
    int quads = (n + 3) / 4;                 // 4 elements per thread
    int threads = 256;
    int blocks = (quads + threads - 1) / threads;  // 4096 for N=4194304
    if (blocks > 8192) blocks = 8192;        // g_partials capacity (N fits anyway)

    giou_fused_kernel<<<blocks, threads>>>(x, y, (float*)d_out, n);
}

// round 7
// speedup vs baseline: 1.1905x; 1.0709x over previous
#include <cuda_runtime.h>

#define EPSF 1e-7f
#define ACLIPF (1.0f - 1e-6f)
#define PI_F 3.14159274101257324f

// Scratch for deterministic single-launch reduction (no device allocs allowed).
static __device__ float g_partials[8192];
static __device__ unsigned int g_ticket = 0;   // self-resetting via atomicInc wrap

__device__ __forceinline__ float fsqrt_approx(float x) {   // single MUFU.SQRT
    float r; asm("sqrt.approx.f32 %0, %1;" : "=f"(r) : "f"(x)); return r;
}

// acos approximation for x in [0,1): abs err <= ~6.8e-5
__device__ __forceinline__ float facos_pos(float x) {
    float p = fmaf(x, -0.0187293f, 0.0742610f);
    p = fmaf(x, p, -0.2121144f);
    p = fmaf(x, p, 1.5707288f);
    return fsqrt_approx(1.0f - x) * p;   // 1-x >= 1e-6 after clipping
}

// acos for x in (-1,1) (clipped to +/-ACLIPF)
__device__ __forceinline__ float facos(float x) {
    float v = facos_pos(fabsf(x));
    return (x >= 0.0f) ? v : (PI_F - v);
}

// Branchless circle-GIoU: the clipped-acos lens formula saturates to the
// contained / disjoint values of inter and hull (error ~1e-3 * r^2 worst case,
// only in the saturated regions), so NO predicates or selects are needed.
__device__ __forceinline__ float giou_loss(float cx0, float cy0, float r0,
                                           float cx1, float cy1, float r1) {
    float dx = cx0 - cx1, dy = cy0 - cy1;
    float d2 = fmaf(dx, dx, dy * dy);
    float d2c = fmaxf(d2, EPSF);
    float inv_d = rsqrtf(d2c);

    float r0s = r0 * r0, r1s = r1 * r1;
    float e = r0s - r1s;                 // r0^2 - r1^2
    float rsum  = r0 + r1;
    float rdiff = fabsf(r0 - r1);
    float rsum2  = rsum * rsum;
    float rdiff2 = rdiff * rdiff;

    // cos0 = (d2+e)/(2 d r0), cos1 = (d2-e)/(2 d r1); saturating clips
    float half_invd = 0.5f * inv_d;
    float cos0 = __fdividef((d2 + e) * half_invd, r0);
    cos0 = fminf(fmaxf(cos0, -ACLIPF), ACLIPF);
    float acos0 = facos(cos0);
    float cos1 = __fdividef((d2 - e) * half_invd, r1);
    cos1 = fminf(fmaxf(cos1, -ACLIPF), ACLIPF);
    float acos1 = facos(cos1);

    // t = (rsum^2 - d^2)(d^2 - rdiff^2) > 0 exactly in the lens region
    float sqrt_t = fsqrt_approx(fmaxf((rsum2 - d2c) * (d2c - rdiff2), EPSF));
    // unconditional inter: saturates to pi*rmin^2 (contained) / 0 (disjoint)
    float inter = fmaf(r0s, acos0, fmaf(r1s, acos1, -0.5f * sqrt_t));

    float uni = fmaf(PI_F, r0s + r1s, -inter);

    // unconditional hull: alpha saturates so hull -> pi*rmax^2 when contained
    float alpha = facos_pos(fminf(rdiff * inv_d, ACLIPF));
    float sqrt_h2 = fsqrt_approx(fmaxf(d2 - rdiff2, EPSF));
    float hull = fmaf(rsum, sqrt_h2,
                 fmaf(alpha, -fabsf(e), PI_F * fmaxf(r0s, r1s)));

    // loss = 1 - (inter/U - (hull-uni)/H) with a single divide
    float U = fmaxf(uni, EPSF), H = fmaxf(hull, EPSF);
    float num = fmaf(inter, H, -(hull - uni) * U);
    return 1.0f - __fdividef(num, U * H);
}

// 4 elements per thread via 3 float4 loads per input (coalesced 128-bit over [N,3]).
// __launch_bounds__(256, 8): cap at 32 regs -> 2048 threads/SM resident.
// Last block (ticket pattern) folds g_partials -> out[0] in a fixed order.
__global__ void __launch_bounds__(256, 8) giou_fused_kernel(
    const float* __restrict__ x, const float* __restrict__ y,
    float* __restrict__ out, int n) {
    int quad = blockIdx.x * blockDim.x + threadIdx.x;
    int base = quad * 4;
    float acc = 0.0f;

    if (base + 3 < n) {
        const float4* x4 = (const float4*)x;
        const float4* y4 = (const float4*)y;
        float4 xa = x4[quad * 3 + 0];
        float4 ya = y4[quad * 3 + 0];
        float4 xb = x4[quad * 3 + 1];
        float4 yb = y4[quad * 3 + 1];
        float4 xc = x4[quad * 3 + 2];
        float4 yc = y4[quad * 3 + 2];
        acc += giou_loss(xa.x, xa.y, xa.z, ya.x, ya.y, ya.z);
        acc += giou_loss(xa.w, xb.x, xb.y, ya.w, yb.x, yb.y);
        acc += giou_loss(xb.z, xb.w, xc.x, yb.z, yb.w, yc.x);
        acc += giou_loss(xc.y, xc.z, xc.w, yc.y, yc.z, yc.w);
    } else if (base < n) {
        for (int i = base; i < n; i++) {
            acc += giou_loss(x[3*i], x[3*i+1], x[3*i+2], y[3*i], y[3*i+1], y[3*i+2]);
        }
    }

    // block reduce
    #pragma unroll
    for (int off = 16; off > 0; off >>= 1)
        acc += __shfl_xor_sync(0xFFFFFFFFu, acc, off);

    __shared__ float warp_sums[8];
    __shared__ bool amLast;
    int lane = threadIdx.x & 31;
    int wid  = threadIdx.x >> 5;
    if (lane == 0) warp_sums[wid] = acc;
    __syncthreads();
    if (wid == 0) {
        float v = (lane < 8) ? warp_sums[lane] : 0.0f;
        #pragma unroll
        for (int off = 4; off > 0; off >>= 1)
            v += __shfl_xor_sync(0xFFFFFFFFu, v, off);
        if (lane == 0) {
            g_partials[blockIdx.x] = v;
            __threadfence();
            unsigned int t = atomicInc(&g_ticket, gridDim.x - 1); // wraps to 0 on last
            amLast = (t == gridDim.x - 1);
        }
    }
    __syncthreads();

    if (amLast) {
        __threadfence();
        int nblocks = gridDim.x;
        float a2 = 0.0f;
        for (int i = threadIdx.x; i < nblocks; i += 256)
            a2 += g_partials[i];                      // fixed order -> deterministic
        #pragma unroll
        for (int off = 16; off > 0; off >>= 1)
            a2 += __shfl_xor_sync(0xFFFFFFFFu, a2, off);
        __syncthreads();                              // reuse warp_sums safely
        if (lane == 0) warp_sums[wid] = a2;
        __syncthreads();
        if (wid == 0) {
            float v = (lane < 8) ? warp_sums[lane] : 0.0f;
            #pragma unroll
            for (int off = 4; off > 0; off >>= 1)
                v += __shfl_xor_sync(0xFFFFFFFFu, v, off);
            if (lane == 0) out[0] = v;
        }
    }
}

extern "C" void kernel_launch(void* const* d_in, const int* in_sizes, int n_in,
                              void* d_out, int out_size) {
    const float* x = (const float*)d_in[0];
    const float* y = (const float*)d_in[1];
    int n = in_sizes[0] / 3;                 // number of circle pairs
    int quads = (n + 3) / 4;                 // 4 elements per thread
    int threads = 256;
    int blocks = (quads + threads - 1) / threads;  // 4096 for N=4194304
    if (blocks > 8192) blocks = 8192;        // g_partials capacity (N fits anyway)

    giou_fused_kernel<<<blocks, threads>>>(x, y, (float*)d_out, n);
}